// round 1
// baseline (speedup 1.0000x reference)
#include <cuda_runtime.h>
#include <cuda_bf16.h>
#include <cstddef>

// Problem constants: B=8, C=64, H=W=160, L=25600, Cq=8, GROUPS=4
#define NB 8
#define NC 64
#define NH 160
#define NW 160
#define NL 25600
#define NCQ 8

// ---------------- scratch (device globals; no allocation allowed) ----------------
__device__ float g_q  [NB*NCQ*NL];        // [b][c][h][w]
__device__ float g_k  [NB*NCQ*NL];
__device__ float g_qT [NB*NCQ*NL];        // [b][w][c][h]
__device__ float g_kT [NB*NCQ*NL];
__device__ float g_v  [NB*NC*NL];         // [b][c][h][w]
__device__ float g_vT [NB*NC*NL];         // [b][w][c][h]
__device__ float g_outH[NB*NW*NH*NC];     // [b][w][h][c]
__device__ float g_o  [NB*NC*NL];         // post-conv, pre-BN  [b][c][h][w]
__device__ float g_mW [NB*NH*NW];         // [b][h][w]
__device__ float g_sW [NB*NH*NW];
__device__ float g_M  [NB*NW*NH];         // [b][w][h]
__device__ float g_Z  [NB*NW*NH];
__device__ float g_sum[NC], g_sumsq[NC], g_bna[NC], g_bnb[NC];

// ---------------- K0: zero BN accumulators (must re-run each graph replay) -------
__global__ void k_zero() {
    int t = threadIdx.x;
    if (t < NC) { g_sum[t] = 0.f; g_sumsq[t] = 0.f; }
}

// ---------------- K1: grouped 1x1 convs q,k,v (natural layout) -------------------
__global__ __launch_bounds__(256) void k_qkv(
    const float* __restrict__ x,
    const float* __restrict__ wq, const float* __restrict__ bq,
    const float* __restrict__ wk, const float* __restrict__ bk,
    const float* __restrict__ wv, const float* __restrict__ bv)
{
    __shared__ float swq[128], swk[128], swv[1024], sb[80];
    int t = threadIdx.x;
    for (int i = t; i < 128; i += 256) { swq[i] = wq[i]; swk[i] = wk[i]; }
    for (int i = t; i < 1024; i += 256) swv[i] = wv[i];
    if (t < 8)               sb[t] = bq[t];
    else if (t < 16)         sb[t] = bk[t - 8];
    else if (t < 80)         sb[t] = bv[t - 16];
    __syncthreads();

    int p  = blockIdx.x * 256 + t;           // 0..204799
    int b  = p / NL;
    int hw = p - b * NL;
    const float* xb = x + (size_t)b * NC * NL + hw;

    #pragma unroll
    for (int g = 0; g < 4; g++) {
        float xr[16];
        #pragma unroll
        for (int c = 0; c < 16; c++) xr[c] = xb[(size_t)(16 * g + c) * NL];
        #pragma unroll
        for (int o = 0; o < 2; o++) {
            int oc = 2 * g + o;
            float aq = sb[oc], ak = sb[8 + oc];
            #pragma unroll
            for (int c = 0; c < 16; c++) {
                aq = fmaf(swq[oc * 16 + c], xr[c], aq);
                ak = fmaf(swk[oc * 16 + c], xr[c], ak);
            }
            g_q[((size_t)b * NCQ + oc) * NL + hw] = aq;
            g_k[((size_t)b * NCQ + oc) * NL + hw] = ak;
        }
        #pragma unroll
        for (int o = 0; o < 16; o++) {
            int oc = 16 * g + o;
            float av = sb[16 + oc];
            #pragma unroll
            for (int c = 0; c < 16; c++) av = fmaf(swv[oc * 16 + c], xr[c], av);
            g_v[((size_t)b * NC + oc) * NL + hw] = av;
        }
    }
}

// ---------------- KT: tiled transpose [b][c][h][w] -> [b][w][c][h] ---------------
template <int WHICH>   // 0: q, 1: k, 2: v
__global__ void k_transpose()
{
    constexpr int C = (WHICH == 2) ? 64 : 8;
    const float* src = (WHICH == 0) ? g_q : (WHICH == 1) ? g_k : g_v;
    float*       dst = (WHICH == 0) ? g_qT : (WHICH == 1) ? g_kT : g_vT;

    __shared__ float tile[32][33];
    int w0 = blockIdx.x * 32, h0 = blockIdx.y * 32;
    int bc = blockIdx.z;
    int b = bc / C, c = bc - b * C;
    const float* s = src + (size_t)bc * NL;
    #pragma unroll
    for (int i = threadIdx.y; i < 32; i += 8)
        tile[i][threadIdx.x] = s[(h0 + i) * NW + w0 + threadIdx.x];
    __syncthreads();
    size_t dbase = ((size_t)b * NW) * (size_t)(C * NH) + (size_t)c * NH;
    #pragma unroll
    for (int i = threadIdx.y; i < 32; i += 8)
        dst[dbase + (size_t)(w0 + i) * (C * NH) + h0 + threadIdx.x] = tile[threadIdx.x][i];
}

// ---------------- K2b: per (b,h) — energy_W stats (mW, sW) ----------------------
// smem: qs[8*161] ks[8*161] E[160*161]
__global__ __launch_bounds__(256) void k_ewstats()
{
    extern __shared__ float sm[];
    float* qs = sm;
    float* ks = sm + 1288;
    float* E  = sm + 2576;
    int t = threadIdx.x;
    int b = blockIdx.x / NH, h = blockIdx.x - b * NH;

    for (int i = t; i < NCQ * NW; i += 256) {
        int c = i / NW, w = i - c * NW;
        size_t a = ((size_t)b * NCQ + c) * NL + h * NW + w;
        qs[c * 161 + w] = g_q[a];
        ks[c * 161 + w] = g_k[a];
    }
    __syncthreads();

    int tx = t & 15, ty = t >> 4;
    {
        float acc[10][10];
        #pragma unroll
        for (int i = 0; i < 10; i++)
            #pragma unroll
            for (int j = 0; j < 10; j++) acc[i][j] = 0.f;
        #pragma unroll
        for (int c = 0; c < NCQ; c++) {
            float qv[10], kv[10];
            #pragma unroll
            for (int i = 0; i < 10; i++) qv[i] = qs[c * 161 + ty * 10 + i];
            #pragma unroll
            for (int j = 0; j < 10; j++) kv[j] = ks[c * 161 + tx * 10 + j];
            #pragma unroll
            for (int i = 0; i < 10; i++)
                #pragma unroll
                for (int j = 0; j < 10; j++) acc[i][j] = fmaf(qv[i], kv[j], acc[i][j]);
        }
        #pragma unroll
        for (int i = 0; i < 10; i++)
            #pragma unroll
            for (int j = 0; j < 10; j++)
                E[(ty * 10 + i) * 161 + tx * 10 + j] = acc[i][j];
    }
    __syncthreads();

    int warp = t >> 5, lane = t & 31;
    for (int w = warp; w < NW; w += 8) {
        float ev[5], m = -3.0e38f;
        #pragma unroll
        for (int jj = 0; jj < 5; jj++) { ev[jj] = E[w * 161 + lane + 32 * jj]; m = fmaxf(m, ev[jj]); }
        #pragma unroll
        for (int off = 16; off > 0; off >>= 1) m = fmaxf(m, __shfl_xor_sync(0xffffffffu, m, off));
        float s = 0.f;
        #pragma unroll
        for (int jj = 0; jj < 5; jj++) s += __expf(ev[jj] - m);
        #pragma unroll
        for (int off = 16; off > 0; off >>= 1) s += __shfl_xor_sync(0xffffffffu, s, off);
        if (lane == 0) {
            g_mW[(size_t)blockIdx.x * NW + w] = m;
            g_sW[(size_t)blockIdx.x * NW + w] = s;
        }
    }
}

// ---------------- K3a: per (b,w) — E_H, joint softmax (att_H), out_H ------------
// smem: qs[1288] ks[1288] E[25760] vs[64*161=10304]; staging reuses sm[0..10240)
__global__ __launch_bounds__(256) void k_colpass()
{
    extern __shared__ float sm[];
    float* qs = sm;
    float* ks = sm + 1288;
    float* E  = sm + 2576;
    float* vs = sm + 28336;
    int t = threadIdx.x;
    int b = blockIdx.x / NW, w = blockIdx.x - b * NW;

    {
        size_t base = (size_t)blockIdx.x * (NCQ * NH);
        for (int i = t; i < NCQ * NH; i += 256) {
            int c = i / NH, h = i - c * NH;
            qs[c * 161 + h] = g_qT[base + i];
            ks[c * 161 + h] = g_kT[base + i];
        }
        size_t vb = (size_t)blockIdx.x * (NC * NH);
        for (int i = t; i < NC * NH; i += 256) {
            int c = i / NH, j = i - c * NH;
            vs[c * 161 + j] = g_vT[vb + i];
        }
    }
    __syncthreads();

    int tx = t & 15, ty = t >> 4;
    {   // E_H[h][j] = sum_c qcol[c][h]*kcol[c][j], masked diag
        float acc[10][10];
        #pragma unroll
        for (int i = 0; i < 10; i++)
            #pragma unroll
            for (int j = 0; j < 10; j++) acc[i][j] = 0.f;
        #pragma unroll
        for (int c = 0; c < NCQ; c++) {
            float qv[10], kv[10];
            #pragma unroll
            for (int i = 0; i < 10; i++) qv[i] = qs[c * 161 + ty * 10 + i];
            #pragma unroll
            for (int j = 0; j < 10; j++) kv[j] = ks[c * 161 + tx * 10 + j];
            #pragma unroll
            for (int i = 0; i < 10; i++)
                #pragma unroll
                for (int j = 0; j < 10; j++) acc[i][j] = fmaf(qv[i], kv[j], acc[i][j]);
        }
        #pragma unroll
        for (int i = 0; i < 10; i++) {
            int h = ty * 10 + i;
            #pragma unroll
            for (int j = 0; j < 10; j++) {
                int jc = tx * 10 + j;
                E[h * 161 + jc] = (jc == h) ? -1.0e30f : acc[i][j];
            }
        }
    }
    __syncthreads();

    // joint softmax: combine with row-pass stats; att_H in place; store M, Z
    int warp = t >> 5, lane = t & 31;
    for (int h = warp; h < NH; h += 8) {
        float mw = g_mW[((size_t)b * NH + h) * NW + w];
        float sw = g_sW[((size_t)b * NH + h) * NW + w];
        float ev[5], m = mw;
        #pragma unroll
        for (int jj = 0; jj < 5; jj++) { ev[jj] = E[h * 161 + lane + 32 * jj]; m = fmaxf(m, ev[jj]); }
        #pragma unroll
        for (int off = 16; off > 0; off >>= 1) m = fmaxf(m, __shfl_xor_sync(0xffffffffu, m, off));
        float s = 0.f;
        #pragma unroll
        for (int jj = 0; jj < 5; jj++) { ev[jj] = __expf(ev[jj] - m); s += ev[jj]; }
        #pragma unroll
        for (int off = 16; off > 0; off >>= 1) s += __shfl_xor_sync(0xffffffffu, s, off);
        float Z   = s + sw * __expf(mw - m);
        float inv = 1.f / Z;
        #pragma unroll
        for (int jj = 0; jj < 5; jj++) E[h * 161 + lane + 32 * jj] = ev[jj] * inv;
        if (lane == 0) {
            g_M[(size_t)blockIdx.x * NH + h] = m;
            g_Z[(size_t)blockIdx.x * NH + h] = Z;
        }
    }
    __syncthreads();

    // out_H[c][h] = sum_j vcol[c][j]*att_H[h][j]   (c = ty*4+a, h = tx+16r)
    float acc[4][10];
    #pragma unroll
    for (int a = 0; a < 4; a++)
        #pragma unroll
        for (int r = 0; r < 10; r++) acc[a][r] = 0.f;
    for (int j = 0; j < NH; j++) {
        float vv[4], av[10];
        #pragma unroll
        for (int a = 0; a < 4; a++) vv[a] = vs[(ty * 4 + a) * 161 + j];
        #pragma unroll
        for (int r = 0; r < 10; r++) av[r] = E[(tx + 16 * r) * 161 + j];
        #pragma unroll
        for (int a = 0; a < 4; a++)
            #pragma unroll
            for (int r = 0; r < 10; r++) acc[a][r] = fmaf(vv[a], av[r], acc[a][r]);
    }
    __syncthreads();
    #pragma unroll
    for (int a = 0; a < 4; a++)
        #pragma unroll
        for (int r = 0; r < 10; r++)
            sm[(tx + 16 * r) * NC + ty * 4 + a] = acc[a][r];   // staged [h][c]
    __syncthreads();
    {
        size_t obase = (size_t)blockIdx.x * (NH * NC);
        for (int i = t; i < NH * NC; i += 256) g_outH[obase + i] = sm[i];
    }
}

// ---------------- K3b: per (b,h) — att_W, out_W, combine, conv, BN stats --------
__global__ __launch_bounds__(256) void k_rowpass(
    const float* __restrict__ gamma, const float* __restrict__ w1d)
{
    extern __shared__ float sm[];
    __shared__ float sw1[1024];
    __shared__ float csum[NC], csq[NC];
    float* qs = sm;
    float* ks = sm + 1288;
    float* E  = sm + 2576;     // E_W / att_W, then reused for outH slab
    float* vs = sm + 28336;    // v rows, then reused for conv input
    int t = threadIdx.x;
    int b = blockIdx.x / NH, h = blockIdx.x - b * NH;

    for (int i = t; i < 1024; i += 256) sw1[i] = w1d[i];
    if (t < NC) { csum[t] = 0.f; csq[t] = 0.f; }
    for (int i = t; i < NCQ * NW; i += 256) {
        int c = i / NW, w = i - c * NW;
        size_t a = ((size_t)b * NCQ + c) * NL + h * NW + w;
        qs[c * 161 + w] = g_q[a];
        ks[c * 161 + w] = g_k[a];
    }
    for (int i = t; i < NC * NW; i += 256) {
        int c = i / NW, j = i - c * NW;
        vs[c * 161 + j] = g_v[((size_t)b * NC + c) * NL + h * NW + j];
    }
    __syncthreads();

    int tx = t & 15, ty = t >> 4;
    {   // E_W[w][j]
        float acc[10][10];
        #pragma unroll
        for (int i = 0; i < 10; i++)
            #pragma unroll
            for (int j = 0; j < 10; j++) acc[i][j] = 0.f;
        #pragma unroll
        for (int c = 0; c < NCQ; c++) {
            float qv[10], kv[10];
            #pragma unroll
            for (int i = 0; i < 10; i++) qv[i] = qs[c * 161 + ty * 10 + i];
            #pragma unroll
            for (int j = 0; j < 10; j++) kv[j] = ks[c * 161 + tx * 10 + j];
            #pragma unroll
            for (int i = 0; i < 10; i++)
                #pragma unroll
                for (int j = 0; j < 10; j++) acc[i][j] = fmaf(qv[i], kv[j], acc[i][j]);
        }
        #pragma unroll
        for (int i = 0; i < 10; i++)
            #pragma unroll
            for (int j = 0; j < 10; j++)
                E[(ty * 10 + i) * 161 + tx * 10 + j] = acc[i][j];
    }
    __syncthreads();

    int warp = t >> 5, lane = t & 31;
    for (int w = warp; w < NW; w += 8) {
        float M  = g_M[((size_t)b * NW + w) * NH + h];
        float Zi = 1.f / g_Z[((size_t)b * NW + w) * NH + h];
        #pragma unroll
        for (int jj = 0; jj < 5; jj++) {
            int j = lane + 32 * jj;
            E[w * 161 + j] = __expf(E[w * 161 + j] - M) * Zi;
        }
    }
    __syncthreads();

    // out_W[c][w] = sum_j vrow[c][j]*att_W[w][j]
    float acc[4][10];
    #pragma unroll
    for (int a = 0; a < 4; a++)
        #pragma unroll
        for (int r = 0; r < 10; r++) acc[a][r] = 0.f;
    for (int j = 0; j < NW; j++) {
        float vv[4], av[10];
        #pragma unroll
        for (int a = 0; a < 4; a++) vv[a] = vs[(ty * 4 + a) * 161 + j];
        #pragma unroll
        for (int r = 0; r < 10; r++) av[r] = E[(tx + 16 * r) * 161 + j];
        #pragma unroll
        for (int a = 0; a < 4; a++)
            #pragma unroll
            for (int r = 0; r < 10; r++) acc[a][r] = fmaf(vv[a], av[r], acc[a][r]);
    }
    float gm = gamma[0];
    __syncthreads();

    // load out_H slab [w][c] (coalesced 256B chunks) into E region
    float* oh = E;
    for (int i = t; i < NW * NC; i += 256) {
        int w = i >> 6, c = i & 63;
        oh[i] = g_outH[(((size_t)b * NW + w) * NH + h) * NC + c];
    }
    __syncthreads();

    // combine into conv-input buffer ob[c][w] (reuse vs region)
    float* ob = vs;
    #pragma unroll
    for (int a = 0; a < 4; a++)
        #pragma unroll
        for (int r = 0; r < 10; r++) {
            int c = ty * 4 + a, w = tx + 16 * r;
            ob[c * 161 + w] = gm * (acc[a][r] + oh[w * NC + c]);
        }
    __syncthreads();

    // grouped 1x1 conv + write o + BN partial sums
    for (int i = t; i < NC * NW; i += 256) {
        int oc = i / NW, w = i - oc * NW;
        int g = oc >> 4;
        float a = 0.f;
        #pragma unroll
        for (int c = 0; c < 16; c++)
            a = fmaf(sw1[oc * 16 + c], ob[(16 * g + c) * 161 + w], a);
        g_o[((size_t)b * NC + oc) * NL + h * NW + w] = a;
        float s = a, q2 = a * a;   // all lanes in warp share oc (160 % 32 aligned)
        #pragma unroll
        for (int off = 16; off > 0; off >>= 1) {
            s  += __shfl_xor_sync(0xffffffffu, s, off);
            q2 += __shfl_xor_sync(0xffffffffu, q2, off);
        }
        if ((t & 31) == 0) { atomicAdd(&csum[oc], s); atomicAdd(&csq[oc], q2); }
    }
    __syncthreads();
    if (t < NC) { atomicAdd(&g_sum[t], csum[t]); atomicAdd(&g_sumsq[t], csq[t]); }
}

// ---------------- K4: finalize BN scale/shift ------------------------------------
__global__ void k_bnfin(const float* __restrict__ bn_w, const float* __restrict__ bn_b)
{
    int c = threadIdx.x;
    const float invN = 1.f / (float)(NB * NL);
    float mean = g_sum[c] * invN;
    float var  = g_sumsq[c] * invN - mean * mean;
    float a    = bn_w[c] * rsqrtf(var + 1e-5f);
    g_bna[c] = a;
    g_bnb[c] = bn_b[c] - mean * a;
}

// ---------------- K5: BN apply + residual + ReLU ---------------------------------
__global__ __launch_bounds__(256) void k_final(const float* __restrict__ x, float* __restrict__ out)
{
    size_t i = (size_t)blockIdx.x * 256 + threadIdx.x;
    int c = (int)((i / NL) & 63);
    float v = g_o[i] * g_bna[c] + g_bnb[c] + x[i];
    out[i] = v > 0.f ? v : 0.f;
}

// ---------------- host ------------------------------------------------------------
extern "C" void kernel_launch(void* const* d_in, const int* in_sizes, int n_in,
                              void* d_out, int out_size)
{
    (void)in_sizes; (void)n_in; (void)out_size;
    const float* x     = (const float*)d_in[0];
    const float* wq    = (const float*)d_in[1];
    const float* bq    = (const float*)d_in[2];
    const float* wk    = (const float*)d_in[3];
    const float* bk    = (const float*)d_in[4];
    const float* wv    = (const float*)d_in[5];
    const float* bv    = (const float*)d_in[6];
    const float* gamma = (const float*)d_in[7];
    const float* w1d   = (const float*)d_in[8];
    const float* bn_w  = (const float*)d_in[9];
    const float* bn_b  = (const float*)d_in[10];
    float* out = (float*)d_out;

    const int SMEM_EW  = (2576 + 160 * 161) * 4;            // 113,344 B
    const int SMEM_BIG = (2576 + 160 * 161 + 64 * 161) * 4; // 154,560 B
    cudaFuncSetAttribute(k_ewstats, cudaFuncAttributeMaxDynamicSharedMemorySize, SMEM_EW);
    cudaFuncSetAttribute(k_colpass, cudaFuncAttributeMaxDynamicSharedMemorySize, SMEM_BIG);
    cudaFuncSetAttribute(k_rowpass, cudaFuncAttributeMaxDynamicSharedMemorySize, SMEM_BIG);

    k_zero<<<1, 64>>>();
    k_qkv<<<800, 256>>>(x, wq, bq, wk, bk, wv, bv);
    dim3 tb(32, 8);
    k_transpose<0><<<dim3(5, 5, NB * NCQ), tb>>>();
    k_transpose<1><<<dim3(5, 5, NB * NCQ), tb>>>();
    k_transpose<2><<<dim3(5, 5, NB * NC), tb>>>();
    k_ewstats<<<NB * NH, 256, SMEM_EW>>>();
    k_colpass<<<NB * NW, 256, SMEM_BIG>>>();
    k_rowpass<<<NB * NH, 256, SMEM_BIG>>>(gamma, w1d);
    k_bnfin<<<1, 64>>>(bn_w, bn_b);
    k_final<<<NB * NC * NL / 256, 256>>>(x, out);
}

// round 2
// speedup vs baseline: 1.4022x; 1.4022x over previous
#include <cuda_runtime.h>
#include <cuda_bf16.h>
#include <cstddef>

// Problem constants: B=8, C=64, H=W=160, L=25600, Cq=8, GROUPS=4
#define NB 8
#define NC 64
#define NH 160
#define NW 160
#define NL 25600
#define NCQ 8
#define PADR 162   // row pad (floats) for [c][x] / att tiles: 162 -> stride-81 8B units, conflict-free
#define PADS 66    // pad for [h][c] staging

typedef unsigned long long u64;

// ---------------- f32x2 helpers --------------------------------------------------
__device__ __forceinline__ void ffma2(u64 &d, u64 a, u64 b) {
    asm("fma.rn.f32x2 %0, %1, %2, %0;" : "+l"(d) : "l"(a), "l"(b));
}
__device__ __forceinline__ u64 pack2(float x, float y) {
    u64 u; asm("mov.b64 %0, {%1, %2};" : "=l"(u) : "f"(x), "f"(y)); return u;
}
__device__ __forceinline__ float2 unpack2(u64 u) {
    float2 r; asm("mov.b64 {%0, %1}, %2;" : "=f"(r.x), "=f"(r.y) : "l"(u)); return r;
}

#define REDMAX(v) { v = fmaxf(v, __shfl_xor_sync(0xffffffffu, v, 1)); \
                    v = fmaxf(v, __shfl_xor_sync(0xffffffffu, v, 2)); \
                    v = fmaxf(v, __shfl_xor_sync(0xffffffffu, v, 4)); \
                    v = fmaxf(v, __shfl_xor_sync(0xffffffffu, v, 8)); }
#define REDSUM(v) { v += __shfl_xor_sync(0xffffffffu, v, 1); \
                    v += __shfl_xor_sync(0xffffffffu, v, 2); \
                    v += __shfl_xor_sync(0xffffffffu, v, 4); \
                    v += __shfl_xor_sync(0xffffffffu, v, 8); }

// ---------------- scratch (device globals; no allocation allowed) ----------------
__device__ float g_q  [NB*NCQ*NL];        // [b][c][h][w]
__device__ float g_k  [NB*NCQ*NL];
__device__ float g_qT [NB*NCQ*NL];        // [b][w][c][h]
__device__ float g_kT [NB*NCQ*NL];
__device__ float g_v  [NB*NC*NL];         // [b][c][h][w]
__device__ float g_vT [NB*NC*NL];         // [b][w][c][h]
__device__ float g_outH[NB*NH*NW*NC];     // [b][h][w][c]
__device__ float g_o  [NB*NC*NL];         // post-conv, pre-BN  [b][c][h][w]
__device__ float g_mW [NB*NH*NW];         // [b][h][w]
__device__ float g_sW [NB*NH*NW];
__device__ float g_M  [NB*NW*NH];         // [b][w][h]
__device__ float g_Z  [NB*NW*NH];
__device__ float g_sum[NC], g_sumsq[NC], g_bna[NC], g_bnb[NC];

// ---------------- K0: zero BN accumulators ---------------------------------------
__global__ void k_zero() {
    int t = threadIdx.x;
    if (t < NC) { g_sum[t] = 0.f; g_sumsq[t] = 0.f; }
}

// ---------------- K1: grouped 1x1 convs q,k,v ------------------------------------
__global__ __launch_bounds__(256) void k_qkv(
    const float* __restrict__ x,
    const float* __restrict__ wq, const float* __restrict__ bq,
    const float* __restrict__ wk, const float* __restrict__ bk,
    const float* __restrict__ wv, const float* __restrict__ bv)
{
    __shared__ float swq[128], swk[128], swv[1024], sb[80];
    int t = threadIdx.x;
    for (int i = t; i < 128; i += 256) { swq[i] = wq[i]; swk[i] = wk[i]; }
    for (int i = t; i < 1024; i += 256) swv[i] = wv[i];
    if (t < 8)               sb[t] = bq[t];
    else if (t < 16)         sb[t] = bk[t - 8];
    else if (t < 80)         sb[t] = bv[t - 16];
    __syncthreads();

    int p  = blockIdx.x * 256 + t;
    int b  = p / NL;
    int hw = p - b * NL;
    const float* xb = x + (size_t)b * NC * NL + hw;

    #pragma unroll
    for (int g = 0; g < 4; g++) {
        float xr[16];
        #pragma unroll
        for (int c = 0; c < 16; c++) xr[c] = xb[(size_t)(16 * g + c) * NL];
        #pragma unroll
        for (int o = 0; o < 2; o++) {
            int oc = 2 * g + o;
            float aq = sb[oc], ak = sb[8 + oc];
            #pragma unroll
            for (int c = 0; c < 16; c++) {
                aq = fmaf(swq[oc * 16 + c], xr[c], aq);
                ak = fmaf(swk[oc * 16 + c], xr[c], ak);
            }
            g_q[((size_t)b * NCQ + oc) * NL + hw] = aq;
            g_k[((size_t)b * NCQ + oc) * NL + hw] = ak;
        }
        #pragma unroll
        for (int o = 0; o < 16; o++) {
            int oc = 16 * g + o;
            float av = sb[16 + oc];
            #pragma unroll
            for (int c = 0; c < 16; c++) av = fmaf(swv[oc * 16 + c], xr[c], av);
            g_v[((size_t)b * NC + oc) * NL + hw] = av;
        }
    }
}

// ---------------- KT: tiled transpose [b][c][h][w] -> [b][w][c][h] ---------------
template <int WHICH>
__global__ void k_transpose()
{
    constexpr int C = (WHICH == 2) ? 64 : 8;
    const float* src = (WHICH == 0) ? g_q : (WHICH == 1) ? g_k : g_v;
    float*       dst = (WHICH == 0) ? g_qT : (WHICH == 1) ? g_kT : g_vT;

    __shared__ float tile[32][33];
    int w0 = blockIdx.x * 32, h0 = blockIdx.y * 32;
    int bc = blockIdx.z;
    int b = bc / C, c = bc - b * C;
    const float* s = src + (size_t)bc * NL;
    #pragma unroll
    for (int i = threadIdx.y; i < 32; i += 8)
        tile[i][threadIdx.x] = s[(h0 + i) * NW + w0 + threadIdx.x];
    __syncthreads();
    size_t dbase = ((size_t)b * NW) * (size_t)(C * NH) + (size_t)c * NH;
    #pragma unroll
    for (int i = threadIdx.y; i < 8 * 4; i += 8)
        ;
    #pragma unroll
    for (int i = threadIdx.y; i < 32; i += 8)
        dst[dbase + (size_t)(w0 + i) * (C * NH) + h0 + threadIdx.x] = tile[threadIdx.x][i];
}

// ---------------- energy 10x10-per-thread f32x2 matmul ---------------------------
// rows i = tye*5+ii (query index), col pairs p = txe*5+pp (key index j = 2p, 2p+1)
__device__ __forceinline__ void energy10x10(
    const float* __restrict__ qs, const float* __restrict__ ks,
    int txe, int tye, float2 ef[5][5])
{
    u64 acc[5][5];
    #pragma unroll
    for (int i = 0; i < 5; i++)
        #pragma unroll
        for (int j = 0; j < 5; j++) acc[i][j] = 0ull;
    #pragma unroll
    for (int c = 0; c < NCQ; c++) {
        u64 qq[5], k2[5];
        #pragma unroll
        for (int ii = 0; ii < 5; ii++) {
            float q = qs[c * PADR + tye * 5 + ii];
            qq[ii] = pack2(q, q);
        }
        #pragma unroll
        for (int pp = 0; pp < 5; pp++)
            k2[pp] = *(const u64*)&ks[c * PADR + 2 * (txe * 5 + pp)];
        #pragma unroll
        for (int ii = 0; ii < 5; ii++)
            #pragma unroll
            for (int pp = 0; pp < 5; pp++) ffma2(acc[ii][pp], qq[ii], k2[pp]);
    }
    #pragma unroll
    for (int ii = 0; ii < 5; ii++)
        #pragma unroll
        for (int pp = 0; pp < 5; pp++) ef[ii][pp] = unpack2(acc[ii][pp]);
}

// ---------------- att(row-major, PADR) x V([c][j], PADR) -> out[c2][r10] ---------
__device__ __forceinline__ void attv_mm(
    const float* __restrict__ E, const float* __restrict__ vs,
    int txm, int cbase, float out[2][10])
{
    u64 acc[2][10];
    #pragma unroll
    for (int a = 0; a < 2; a++)
        #pragma unroll
        for (int r = 0; r < 10; r++) acc[a][r] = 0ull;
    const float* ap[10];
    const float* vp[2];
    #pragma unroll
    for (int r = 0; r < 10; r++) ap[r] = E + (txm + 16 * r) * PADR;
    #pragma unroll
    for (int a = 0; a < 2; a++) vp[a] = vs + (cbase + a) * PADR;
    #pragma unroll 2
    for (int p = 0; p < 80; p++) {
        u64 a2[10], v2[2];
        #pragma unroll
        for (int r = 0; r < 10; r++) a2[r] = *(const u64*)(ap[r] + 2 * p);
        #pragma unroll
        for (int a = 0; a < 2; a++) v2[a] = *(const u64*)(vp[a] + 2 * p);
        #pragma unroll
        for (int a = 0; a < 2; a++)
            #pragma unroll
            for (int r = 0; r < 10; r++) ffma2(acc[a][r], v2[a], a2[r]);
    }
    #pragma unroll
    for (int a = 0; a < 2; a++)
        #pragma unroll
        for (int r = 0; r < 10; r++) {
            float2 s = unpack2(acc[a][r]);
            out[a][r] = s.x + s.y;
        }
}

// ---------------- K2: per (b,h) — energy_W stats (mW, sW), register-resident -----
__global__ __launch_bounds__(512) void k_ewstats()
{
    __shared__ float qs[NCQ * PADR], ks[NCQ * PADR];
    int t = threadIdx.x;
    int bid = blockIdx.x;
    int b = bid / NH, h = bid - b * NH;

    {
        const float2* gq2 = (const float2*)g_q;
        const float2* gk2 = (const float2*)g_k;
        int base2 = (b * NCQ * NL + h * NW) >> 1;
        for (int i2 = t; i2 < NCQ * 80; i2 += 512) {
            int c = i2 / 80, j2 = i2 - c * 80;
            *(float2*)&qs[c * PADR + 2 * j2] = gq2[base2 + c * (NL >> 1) + j2];
            *(float2*)&ks[c * PADR + 2 * j2] = gk2[base2 + c * (NL >> 1) + j2];
        }
    }
    __syncthreads();

    int txe = t & 15, tye = t >> 4;
    float2 ef[5][5];
    energy10x10(qs, ks, txe, tye, ef);

    #pragma unroll
    for (int ii = 0; ii < 5; ii++) {
        int w = tye * 5 + ii;
        float m = -3.0e38f;
        #pragma unroll
        for (int pp = 0; pp < 5; pp++) m = fmaxf(m, fmaxf(ef[ii][pp].x, ef[ii][pp].y));
        REDMAX(m);
        float s = 0.f;
        #pragma unroll
        for (int pp = 0; pp < 5; pp++)
            s += __expf(ef[ii][pp].x - m) + __expf(ef[ii][pp].y - m);
        REDSUM(s);
        if (txe == 0) {
            g_mW[bid * NW + w] = m;
            g_sW[bid * NW + w] = s;
        }
    }
}

// ---------------- K3a: per (b,w) — E_H, joint softmax, att_H, out_H --------------
__global__ __launch_bounds__(512, 1) void k_colpass()
{
    extern __shared__ __align__(16) float sm[];
    float* qs = sm;                 // 8*162
    float* ks = sm + 1296;          // 8*162
    float* E  = sm + 2592;          // 160*162 att
    float* vs = sm + 28512;         // 64*162
    int t = threadIdx.x;
    int bid = blockIdx.x;
    int b = bid / NW, w = bid - b * NW;

    {
        const float2* gq2 = (const float2*)g_qT;
        const float2* gk2 = (const float2*)g_kT;
        const float2* gv2 = (const float2*)g_vT;
        int base2 = bid * 640;      // 1280/2
        for (int i2 = t; i2 < 640; i2 += 512) {
            int c = i2 / 80, j2 = i2 - c * 80;
            *(float2*)&qs[c * PADR + 2 * j2] = gq2[base2 + i2];
            *(float2*)&ks[c * PADR + 2 * j2] = gk2[base2 + i2];
        }
        int vb2 = bid * 5120;       // 10240/2
        for (int i2 = t; i2 < 5120; i2 += 512) {
            int c = i2 / 80, j2 = i2 - c * 80;
            *(float2*)&vs[c * PADR + 2 * j2] = gv2[vb2 + i2];
        }
    }
    __syncthreads();

    int txe = t & 15, tye = t >> 4;
    float2 ef[5][5];
    energy10x10(qs, ks, txe, tye, ef);

    // joint softmax per row h (half-warp owns a row)
    #pragma unroll
    for (int ii = 0; ii < 5; ii++) {
        int h = tye * 5 + ii;
        float mw = g_mW[(b * NH + h) * NW + w];
        float sw = g_sW[(b * NH + h) * NW + w];
        float m = mw;
        #pragma unroll
        for (int pp = 0; pp < 5; pp++) {
            int j0 = 2 * (txe * 5 + pp);
            if (j0     == h) ef[ii][pp].x = -1.0e30f;
            if (j0 + 1 == h) ef[ii][pp].y = -1.0e30f;
            m = fmaxf(m, fmaxf(ef[ii][pp].x, ef[ii][pp].y));
        }
        REDMAX(m);
        float s = 0.f;
        #pragma unroll
        for (int pp = 0; pp < 5; pp++) {
            ef[ii][pp].x = __expf(ef[ii][pp].x - m);
            ef[ii][pp].y = __expf(ef[ii][pp].y - m);
            s += ef[ii][pp].x + ef[ii][pp].y;
        }
        REDSUM(s);
        float Z = s + sw * __expf(mw - m);
        float inv = 1.f / Z;
        if (txe == 0) {
            g_M[bid * NH + h] = m;
            g_Z[bid * NH + h] = Z;
        }
        #pragma unroll
        for (int pp = 0; pp < 5; pp++)
            *(float2*)&E[h * PADR + 2 * (txe * 5 + pp)] =
                make_float2(ef[ii][pp].x * inv, ef[ii][pp].y * inv);
    }
    __syncthreads();

    int txm = t & 15, cbit = (t >> 4) & 1, tym = t >> 5;
    int cbase = tym * 4 + cbit * 2;
    float out[2][10];
    attv_mm(E, vs, txm, cbase, out);
    __syncthreads();

    // stage [h][c] (pad 66) in E region, then coalesced write to g_outH[b][h][w][c]
    #pragma unroll
    for (int a = 0; a < 2; a++)
        #pragma unroll
        for (int r = 0; r < 10; r++)
            E[(txm + 16 * r) * PADS + cbase + a] = out[a][r];
    __syncthreads();
    for (int i = t; i < NH * NC; i += 512) {
        int h = i >> 6, c = i & 63;
        g_outH[(((size_t)b * NH + h) * NW + w) * NC + c] = E[h * PADS + c];
    }
}

// ---------------- K3b: per (b,h) — att_W, out_W, combine, conv, BN stats ---------
__global__ __launch_bounds__(512, 1) void k_rowpass(
    const float* __restrict__ gamma, const float* __restrict__ w1d)
{
    extern __shared__ __align__(16) float sm[];
    __shared__ float sw1[1024];
    __shared__ float csum[NC], csq[NC];
    float* qs = sm;
    float* ks = sm + 1296;
    float* E  = sm + 2592;     // att_W, then out_H slab
    float* vs = sm + 28512;    // v rows, then conv input
    int t = threadIdx.x;
    int bid = blockIdx.x;
    int b = bid / NH, h = bid - b * NH;

    for (int i = t; i < 1024; i += 512) sw1[i] = w1d[i];
    if (t < NC) { csum[t] = 0.f; csq[t] = 0.f; }
    {
        const float2* gq2 = (const float2*)g_q;
        const float2* gk2 = (const float2*)g_k;
        const float2* gv2 = (const float2*)g_v;
        int base2 = (b * NCQ * NL + h * NW) >> 1;
        for (int i2 = t; i2 < NCQ * 80; i2 += 512) {
            int c = i2 / 80, j2 = i2 - c * 80;
            *(float2*)&qs[c * PADR + 2 * j2] = gq2[base2 + c * (NL >> 1) + j2];
            *(float2*)&ks[c * PADR + 2 * j2] = gk2[base2 + c * (NL >> 1) + j2];
        }
        int vbase2 = (b * NC * NL + h * NW) >> 1;
        for (int i2 = t; i2 < NC * 80; i2 += 512) {
            int c = i2 / 80, j2 = i2 - c * 80;
            *(float2*)&vs[c * PADR + 2 * j2] = gv2[vbase2 + c * (NL >> 1) + j2];
        }
    }
    __syncthreads();

    int txe = t & 15, tye = t >> 4;
    float2 ef[5][5];
    energy10x10(qs, ks, txe, tye, ef);

    // att_W = exp(E_W - M)/Z using joint stats from colpass
    #pragma unroll
    for (int ii = 0; ii < 5; ii++) {
        int w = tye * 5 + ii;
        float M  = g_M[(b * NW + w) * NH + h];
        float Zi = 1.f / g_Z[(b * NW + w) * NH + h];
        #pragma unroll
        for (int pp = 0; pp < 5; pp++)
            *(float2*)&E[w * PADR + 2 * (txe * 5 + pp)] =
                make_float2(__expf(ef[ii][pp].x - M) * Zi,
                            __expf(ef[ii][pp].y - M) * Zi);
    }
    __syncthreads();

    int txm = t & 15, cbit = (t >> 4) & 1, tym = t >> 5;
    int cbase = tym * 4 + cbit * 2;
    float ow[2][10];
    attv_mm(E, vs, txm, cbase, ow);
    float gm = gamma[0];
    __syncthreads();

    // load out_H slab (contiguous) into E region staged [w][c] pad 66
    {
        const float2* goh2 = (const float2*)(g_outH + ((size_t)b * NH + h) * NW * NC);
        for (int i2 = t; i2 < (NW * NC) / 2; i2 += 512) {
            int w = i2 >> 5, c2 = i2 & 31;
            *(float2*)&E[w * PADS + 2 * c2] = goh2[i2];
        }
    }
    __syncthreads();

    // combine into conv-input ob[c][w] (vs region, v fully consumed)
    #pragma unroll
    for (int a = 0; a < 2; a++)
        #pragma unroll
        for (int r = 0; r < 10; r++) {
            int c = cbase + a, w = txm + 16 * r;
            vs[c * PADR + w] = gm * (ow[a][r] + E[w * PADS + c]);
        }
    __syncthreads();

    // grouped 1x1 conv + write o + BN partial sums (warp-uniform oc: 160 = 5*32)
    for (int i = t; i < NC * NW; i += 512) {
        int oc = i / NW, w = i - oc * NW;
        int g = oc >> 4;
        float a = 0.f;
        #pragma unroll
        for (int c = 0; c < 16; c++)
            a = fmaf(sw1[oc * 16 + c], vs[(16 * g + c) * PADR + w], a);
        g_o[((size_t)b * NC + oc) * NL + h * NW + w] = a;
        float s = a, q2 = a * a;
        #pragma unroll
        for (int off = 16; off > 0; off >>= 1) {
            s  += __shfl_xor_sync(0xffffffffu, s, off);
            q2 += __shfl_xor_sync(0xffffffffu, q2, off);
        }
        if ((t & 31) == 0) { atomicAdd(&csum[oc], s); atomicAdd(&csq[oc], q2); }
    }
    __syncthreads();
    if (t < NC) { atomicAdd(&g_sum[t], csum[t]); atomicAdd(&g_sumsq[t], csq[t]); }
}

// ---------------- K4: finalize BN scale/shift ------------------------------------
__global__ void k_bnfin(const float* __restrict__ bn_w, const float* __restrict__ bn_b)
{
    int c = threadIdx.x;
    const float invN = 1.f / (float)(NB * NL);
    float mean = g_sum[c] * invN;
    float var  = g_sumsq[c] * invN - mean * mean;
    float a    = bn_w[c] * rsqrtf(var + 1e-5f);
    g_bna[c] = a;
    g_bnb[c] = bn_b[c] - mean * a;
}

// ---------------- K5: BN apply + residual + ReLU (float4) ------------------------
__global__ __launch_bounds__(256) void k_final(const float* __restrict__ x, float* __restrict__ out)
{
    int i = blockIdx.x * 256 + threadIdx.x;          // float4 index, < 3276800
    int c = (i / 6400) & 63;                          // NL/4 = 6400
    float a = g_bna[c], bb = g_bnb[c];
    float4 o = ((const float4*)g_o)[i];
    float4 xv = ((const float4*)x)[i];
    float4 r;
    r.x = fmaf(o.x, a, bb) + xv.x; r.x = r.x > 0.f ? r.x : 0.f;
    r.y = fmaf(o.y, a, bb) + xv.y; r.y = r.y > 0.f ? r.y : 0.f;
    r.z = fmaf(o.z, a, bb) + xv.z; r.z = r.z > 0.f ? r.z : 0.f;
    r.w = fmaf(o.w, a, bb) + xv.w; r.w = r.w > 0.f ? r.w : 0.f;
    ((float4*)out)[i] = r;
}

// ---------------- host ------------------------------------------------------------
extern "C" void kernel_launch(void* const* d_in, const int* in_sizes, int n_in,
                              void* d_out, int out_size)
{
    (void)in_sizes; (void)n_in; (void)out_size;
    const float* x     = (const float*)d_in[0];
    const float* wq    = (const float*)d_in[1];
    const float* bq    = (const float*)d_in[2];
    const float* wk    = (const float*)d_in[3];
    const float* bk    = (const float*)d_in[4];
    const float* wv    = (const float*)d_in[5];
    const float* bv    = (const float*)d_in[6];
    const float* gamma = (const float*)d_in[7];
    const float* w1d   = (const float*)d_in[8];
    const float* bn_w  = (const float*)d_in[9];
    const float* bn_b  = (const float*)d_in[10];
    float* out = (float*)d_out;

    const int SMEM_BIG = (1296 * 2 + 160 * PADR + 64 * PADR) * 4;  // 155,520 B
    cudaFuncSetAttribute(k_colpass, cudaFuncAttributeMaxDynamicSharedMemorySize, SMEM_BIG);
    cudaFuncSetAttribute(k_rowpass, cudaFuncAttributeMaxDynamicSharedMemorySize, SMEM_BIG);

    k_zero<<<1, 64>>>();
    k_qkv<<<800, 256>>>(x, wq, bq, wk, bk, wv, bv);
    dim3 tb(32, 8);
    k_transpose<0><<<dim3(5, 5, NB * NCQ), tb>>>();
    k_transpose<1><<<dim3(5, 5, NB * NCQ), tb>>>();
    k_transpose<2><<<dim3(5, 5, NB * NC), tb>>>();
    k_ewstats<<<NB * NH, 512>>>();
    k_colpass<<<NB * NW, 512, SMEM_BIG>>>();
    k_rowpass<<<NB * NH, 512, SMEM_BIG>>>(gamma, w1d);
    k_bnfin<<<1, 64>>>(bn_w, bn_b);
    k_final<<<(NB * NC * NL) / 1024, 256>>>(x, out);
}

// round 5
// speedup vs baseline: 1.6447x; 1.1729x over previous
#include <cuda_runtime.h>
#include <cuda_bf16.h>
#include <cstddef>

// Problem constants: B=8, C=64, H=W=160, L=25600, Cq=8, GROUPS=4
#define NB 8
#define NC 64
#define NH 160
#define NW 160
#define NL 25600
#define NCQ 8
#define PADR 162   // row pad (floats): stride 648B; 5-row step 40 mod 128, 4-row step 32 mod 128 -> conflict-free tiles
#define PADS 66    // pad for [h][c] staging

typedef unsigned long long u64;

// ---------------- f32x2 helpers --------------------------------------------------
__device__ __forceinline__ void ffma2(u64 &d, u64 a, u64 b) {
    asm("fma.rn.f32x2 %0, %1, %2, %0;" : "+l"(d) : "l"(a), "l"(b));
}
__device__ __forceinline__ u64 pack2(float x, float y) {
    u64 u; asm("mov.b64 %0, {%1, %2};" : "=l"(u) : "f"(x), "f"(y)); return u;
}
__device__ __forceinline__ float2 unpack2(u64 u) {
    float2 r; asm("mov.b64 {%0, %1}, %2;" : "=f"(r.x), "=f"(r.y) : "l"(u)); return r;
}

#define REDMAX(v) { v = fmaxf(v, __shfl_xor_sync(0xffffffffu, v, 1)); \
                    v = fmaxf(v, __shfl_xor_sync(0xffffffffu, v, 2)); \
                    v = fmaxf(v, __shfl_xor_sync(0xffffffffu, v, 4)); \
                    v = fmaxf(v, __shfl_xor_sync(0xffffffffu, v, 8)); }
#define REDSUM(v) { v += __shfl_xor_sync(0xffffffffu, v, 1); \
                    v += __shfl_xor_sync(0xffffffffu, v, 2); \
                    v += __shfl_xor_sync(0xffffffffu, v, 4); \
                    v += __shfl_xor_sync(0xffffffffu, v, 8); }

// ---------------- scratch (device globals; no allocation allowed) ----------------
__device__ float g_q  [NB*NCQ*NL];        // [b][c][h][w]
__device__ float g_k  [NB*NCQ*NL];
__device__ float g_qT [NB*NCQ*NL];        // [b][w][c][h]
__device__ float g_kT [NB*NCQ*NL];
__device__ float g_v  [NB*NC*NL];         // [b][c][h][w]
__device__ float g_vT [NB*NC*NL];         // [b][w][c][h]
__device__ float g_outH[NB*NH*NW*NC];     // [b][h][w][c]
__device__ float g_o  [NB*NC*NL];         // post-conv, pre-BN  [b][c][h][w]
__device__ float g_mW [NB*NH*NW];         // [b][h][w]
__device__ float g_sW [NB*NH*NW];
__device__ float g_M  [NB*NW*NH];         // [b][w][h]
__device__ float g_Z  [NB*NW*NH];
__device__ float g_sum[NC], g_sumsq[NC], g_bna[NC], g_bnb[NC];

// ---------------- K0: zero BN accumulators ---------------------------------------
__global__ void k_zero() {
    int t = threadIdx.x;
    if (t < NC) { g_sum[t] = 0.f; g_sumsq[t] = 0.f; }
}

// ---------------- K1: grouped 1x1 convs q,k,v (float4, 4 pixels/thread) ----------
__global__ __launch_bounds__(128) void k_qkv(
    const float* __restrict__ x,
    const float* __restrict__ wq, const float* __restrict__ bq,
    const float* __restrict__ wk, const float* __restrict__ bk,
    const float* __restrict__ wv, const float* __restrict__ bv)
{
    __shared__ float swq[128], swk[128], swv[1024], sb[80];
    int t = threadIdx.x;
    for (int i = t; i < 128; i += 128) { swq[i] = wq[i]; swk[i] = wk[i]; }
    for (int i = t; i < 1024; i += 128) swv[i] = wv[i];
    if (t < 8)               sb[t] = bq[t];
    else if (t < 16)         sb[t] = bk[t - 8];
    else if (t < 80)         sb[t] = bv[t - 16];
    __syncthreads();

    int p  = blockIdx.x * 128 + t;        // quad index, 0..51199
    int b  = p / 6400;
    int q4 = p - b * 6400;
    const float4* xb = (const float4*)(x + (size_t)b * NC * NL) + q4;

    #pragma unroll
    for (int g = 0; g < 4; g++) {
        float4 xr[16];
        #pragma unroll
        for (int c = 0; c < 16; c++) xr[c] = xb[(size_t)(16 * g + c) * 6400];
        #pragma unroll
        for (int o = 0; o < 2; o++) {
            int oc = 2 * g + o;
            float bqv = sb[oc], bkv = sb[8 + oc];
            float4 aq = make_float4(bqv, bqv, bqv, bqv);
            float4 ak = make_float4(bkv, bkv, bkv, bkv);
            #pragma unroll
            for (int c = 0; c < 16; c++) {
                float wqv = swq[oc * 16 + c], wkv = swk[oc * 16 + c];
                aq.x = fmaf(wqv, xr[c].x, aq.x); aq.y = fmaf(wqv, xr[c].y, aq.y);
                aq.z = fmaf(wqv, xr[c].z, aq.z); aq.w = fmaf(wqv, xr[c].w, aq.w);
                ak.x = fmaf(wkv, xr[c].x, ak.x); ak.y = fmaf(wkv, xr[c].y, ak.y);
                ak.z = fmaf(wkv, xr[c].z, ak.z); ak.w = fmaf(wkv, xr[c].w, ak.w);
            }
            ((float4*)g_q)[((size_t)b * NCQ + oc) * 6400 + q4] = aq;
            ((float4*)g_k)[((size_t)b * NCQ + oc) * 6400 + q4] = ak;
        }
        #pragma unroll
        for (int o = 0; o < 16; o++) {
            int oc = 16 * g + o;
            float bv0 = sb[16 + oc];
            float4 av = make_float4(bv0, bv0, bv0, bv0);
            #pragma unroll
            for (int c = 0; c < 16; c++) {
                float wv0 = swv[oc * 16 + c];
                av.x = fmaf(wv0, xr[c].x, av.x); av.y = fmaf(wv0, xr[c].y, av.y);
                av.z = fmaf(wv0, xr[c].z, av.z); av.w = fmaf(wv0, xr[c].w, av.w);
            }
            ((float4*)g_v)[((size_t)b * NC + oc) * 6400 + q4] = av;
        }
    }
}

// ---------------- KT: merged tiled transpose [b][c][h][w] -> [b][w][c][h] --------
// z layout: [0,64) q (C=8), [64,128) k (C=8), [128,640) v (C=64)
__global__ void k_transpose_all()
{
    __shared__ float tile[32][33];
    int z = blockIdx.z;
    const float* src; float* dst; int C, bc;
    if (z < 64)       { src = g_q; dst = g_qT; C = 8;  bc = z; }
    else if (z < 128) { src = g_k; dst = g_kT; C = 8;  bc = z - 64; }
    else              { src = g_v; dst = g_vT; C = 64; bc = z - 128; }
    int b = bc / C, c = bc - b * C;
    int w0 = blockIdx.x * 32, h0 = blockIdx.y * 32;
    const float* s = src + (size_t)bc * NL;
    #pragma unroll
    for (int i = threadIdx.y; i < 32; i += 8)
        tile[i][threadIdx.x] = s[(h0 + i) * NW + w0 + threadIdx.x];
    __syncthreads();
    size_t dbase = ((size_t)b * NW) * (size_t)(C * NH) + (size_t)c * NH;
    #pragma unroll
    for (int i = threadIdx.y; i < 32; i += 8)
        dst[dbase + (size_t)(w0 + i) * (C * NH) + h0 + threadIdx.x] = tile[threadIdx.x][i];
}

// ---------------- energy 10x10-per-thread f32x2 matmul ---------------------------
__device__ __forceinline__ void energy10x10(
    const float* __restrict__ qs, const float* __restrict__ ks,
    int txe, int tye, float2 ef[5][5])
{
    u64 acc[5][5];
    #pragma unroll
    for (int i = 0; i < 5; i++)
        #pragma unroll
        for (int j = 0; j < 5; j++) acc[i][j] = 0ull;
    #pragma unroll
    for (int c = 0; c < NCQ; c++) {
        u64 qq[5], k2[5];
        #pragma unroll
        for (int ii = 0; ii < 5; ii++) {
            float q = qs[c * PADR + tye * 5 + ii];
            qq[ii] = pack2(q, q);
        }
        #pragma unroll
        for (int pp = 0; pp < 5; pp++)
            k2[pp] = *(const u64*)&ks[c * PADR + 2 * (txe * 5 + pp)];
        #pragma unroll
        for (int ii = 0; ii < 5; ii++)
            #pragma unroll
            for (int pp = 0; pp < 5; pp++) ffma2(acc[ii][pp], qq[ii], k2[pp]);
    }
    #pragma unroll
    for (int ii = 0; ii < 5; ii++)
        #pragma unroll
        for (int pp = 0; pp < 5; pp++) ef[ii][pp] = unpack2(acc[ii][pp]);
}

// ---------------- att x V warp-blocked matmul ------------------------------------
// warp block: 16 channels x 40 rows; thread: 4 channels x 5 rows.
// c = (warp&3)*16 + (lane&3)*4 + a ; row = (warp>>2)*40 + (lane>>2)*5 + r
__device__ __forceinline__ void attv16x40(
    const float* __restrict__ E, const float* __restrict__ vs,
    int warp, int lane, float out[4][5])
{
    int cb = (warp & 3) * 16 + (lane & 3) * 4;
    int hb = (warp >> 2) * 40 + (lane >> 2) * 5;
    u64 acc[4][5];
    #pragma unroll
    for (int a = 0; a < 4; a++)
        #pragma unroll
        for (int r = 0; r < 5; r++) acc[a][r] = 0ull;
    const float* ap[5];
    const float* vp[4];
    #pragma unroll
    for (int r = 0; r < 5; r++) ap[r] = E + (hb + r) * PADR;
    #pragma unroll
    for (int a = 0; a < 4; a++) vp[a] = vs + (cb + a) * PADR;
    #pragma unroll 2
    for (int p = 0; p < 80; p++) {
        u64 a2[5], v2[4];
        #pragma unroll
        for (int r = 0; r < 5; r++) a2[r] = *(const u64*)(ap[r] + 2 * p);
        #pragma unroll
        for (int a = 0; a < 4; a++) v2[a] = *(const u64*)(vp[a] + 2 * p);
        #pragma unroll
        for (int a = 0; a < 4; a++)
            #pragma unroll
            for (int r = 0; r < 5; r++) ffma2(acc[a][r], v2[a], a2[r]);
    }
    #pragma unroll
    for (int a = 0; a < 4; a++)
        #pragma unroll
        for (int r = 0; r < 5; r++) {
            float2 s = unpack2(acc[a][r]);
            out[a][r] = s.x + s.y;
        }
}

// ---------------- K2: per (b,h) — energy_W stats (mW, sW), register-resident -----
__global__ __launch_bounds__(512) void k_ewstats()
{
    __shared__ float qs[NCQ * PADR], ks[NCQ * PADR];
    int t = threadIdx.x;
    int bid = blockIdx.x;
    int b = bid / NH, h = bid - b * NH;

    {
        const float2* gq2 = (const float2*)g_q;
        const float2* gk2 = (const float2*)g_k;
        int base2 = (b * NCQ * NL + h * NW) >> 1;
        for (int i2 = t; i2 < NCQ * 80; i2 += 512) {
            int c = i2 / 80, j2 = i2 - c * 80;
            *(float2*)&qs[c * PADR + 2 * j2] = gq2[base2 + c * (NL >> 1) + j2];
            *(float2*)&ks[c * PADR + 2 * j2] = gk2[base2 + c * (NL >> 1) + j2];
        }
    }
    __syncthreads();

    int txe = t & 15, tye = t >> 4;
    float2 ef[5][5];
    energy10x10(qs, ks, txe, tye, ef);

    #pragma unroll
    for (int ii = 0; ii < 5; ii++) {
        int w = tye * 5 + ii;
        float m = -3.0e38f;
        #pragma unroll
        for (int pp = 0; pp < 5; pp++) m = fmaxf(m, fmaxf(ef[ii][pp].x, ef[ii][pp].y));
        REDMAX(m);
        float s = 0.f;
        #pragma unroll
        for (int pp = 0; pp < 5; pp++)
            s += __expf(ef[ii][pp].x - m) + __expf(ef[ii][pp].y - m);
        REDSUM(s);
        if (txe == 0) {
            g_mW[bid * NW + w] = m;
            g_sW[bid * NW + w] = s;
        }
    }
}

// ---------------- K3a: per (b,w) — E_H, joint softmax, att_H, out_H --------------
__global__ __launch_bounds__(512, 1) void k_colpass()
{
    extern __shared__ __align__(16) float sm[];
    float* qs = sm;                 // 8*162
    float* ks = sm + 1296;          // 8*162
    float* E  = sm + 2592;          // 160*162 att, later [h][c] staging
    float* vs = sm + 28512;         // 64*162
    int t = threadIdx.x;
    int bid = blockIdx.x;
    int b = bid / NW, w = bid - b * NW;

    {
        const float2* gq2 = (const float2*)g_qT;
        const float2* gk2 = (const float2*)g_kT;
        const float2* gv2 = (const float2*)g_vT;
        int base2 = bid * 640;
        for (int i2 = t; i2 < 640; i2 += 512) {
            int c = i2 / 80, j2 = i2 - c * 80;
            *(float2*)&qs[c * PADR + 2 * j2] = gq2[base2 + i2];
            *(float2*)&ks[c * PADR + 2 * j2] = gk2[base2 + i2];
        }
        int vb2 = bid * 5120;
        for (int i2 = t; i2 < 5120; i2 += 512) {
            int c = i2 / 80, j2 = i2 - c * 80;
            *(float2*)&vs[c * PADR + 2 * j2] = gv2[vb2 + i2];
        }
    }
    __syncthreads();

    int txe = t & 15, tye = t >> 4;
    float2 ef[5][5];
    energy10x10(qs, ks, txe, tye, ef);

    // joint softmax per row h (half-warp owns a row)
    #pragma unroll
    for (int ii = 0; ii < 5; ii++) {
        int h = tye * 5 + ii;
        float mw = g_mW[(b * NH + h) * NW + w];
        float sw = g_sW[(b * NH + h) * NW + w];
        float m = mw;
        #pragma unroll
        for (int pp = 0; pp < 5; pp++) {
            int j0 = 2 * (txe * 5 + pp);
            if (j0     == h) ef[ii][pp].x = -1.0e30f;
            if (j0 + 1 == h) ef[ii][pp].y = -1.0e30f;
            m = fmaxf(m, fmaxf(ef[ii][pp].x, ef[ii][pp].y));
        }
        REDMAX(m);
        float s = 0.f;
        #pragma unroll
        for (int pp = 0; pp < 5; pp++) {
            ef[ii][pp].x = __expf(ef[ii][pp].x - m);
            ef[ii][pp].y = __expf(ef[ii][pp].y - m);
            s += ef[ii][pp].x + ef[ii][pp].y;
        }
        REDSUM(s);
        float Z = s + sw * __expf(mw - m);
        float inv = 1.f / Z;
        if (txe == 0) {
            g_M[bid * NH + h] = m;
            g_Z[bid * NH + h] = Z;
        }
        #pragma unroll
        for (int pp = 0; pp < 5; pp++)
            *(float2*)&E[h * PADR + 2 * (txe * 5 + pp)] =
                make_float2(ef[ii][pp].x * inv, ef[ii][pp].y * inv);
    }
    __syncthreads();

    int warp = t >> 5, lane = t & 31;
    float out[4][5];
    attv16x40(E, vs, warp, lane, out);
    __syncthreads();

    // stage [h][c] (pad 66) in E region, then coalesced write to g_outH[b][h][w][c]
    {
        int cb = (warp & 3) * 16 + (lane & 3) * 4;
        int hb = (warp >> 2) * 40 + (lane >> 2) * 5;
        #pragma unroll
        for (int a = 0; a < 4; a++)
            #pragma unroll
            for (int r = 0; r < 5; r++)
                E[(hb + r) * PADS + cb + a] = out[a][r];
    }
    __syncthreads();
    for (int i = t; i < NH * NC; i += 512) {
        int h = i >> 6, c = i & 63;
        g_outH[(((size_t)b * NH + h) * NW + w) * NC + c] = E[h * PADS + c];
    }
}

// ---------------- K3b: per (b,h) — att_W, out_W, combine, conv, BN stats ---------
__global__ __launch_bounds__(512, 1) void k_rowpass(
    const float* __restrict__ gamma, const float* __restrict__ w1d)
{
    extern __shared__ __align__(16) float sm[];
    __shared__ float sw1[1024];
    __shared__ float csum[NC], csq[NC];
    float* qs = sm;
    float* ks = sm + 1296;
    float* E  = sm + 2592;     // att_W, then out_H slab
    float* vs = sm + 28512;    // v rows, then conv input
    int t = threadIdx.x;
    int bid = blockIdx.x;
    int b = bid / NH, h = bid - b * NH;

    for (int i = t; i < 1024; i += 512) sw1[i] = w1d[i];
    if (t < NC) { csum[t] = 0.f; csq[t] = 0.f; }
    {
        const float2* gq2 = (const float2*)g_q;
        const float2* gk2 = (const float2*)g_k;
        const float2* gv2 = (const float2*)g_v;
        int base2 = (b * NCQ * NL + h * NW) >> 1;
        for (int i2 = t; i2 < NCQ * 80; i2 += 512) {
            int c = i2 / 80, j2 = i2 - c * 80;
            *(float2*)&qs[c * PADR + 2 * j2] = gq2[base2 + c * (NL >> 1) + j2];
            *(float2*)&ks[c * PADR + 2 * j2] = gk2[base2 + c * (NL >> 1) + j2];
        }
        int vbase2 = (b * NC * NL + h * NW) >> 1;
        for (int i2 = t; i2 < NC * 80; i2 += 512) {
            int c = i2 / 80, j2 = i2 - c * 80;
            *(float2*)&vs[c * PADR + 2 * j2] = gv2[vbase2 + c * (NL >> 1) + j2];
        }
    }
    __syncthreads();

    int txe = t & 15, tye = t >> 4;
    float2 ef[5][5];
    energy10x10(qs, ks, txe, tye, ef);

    // att_W = exp(E_W - M)/Z using joint stats from colpass
    #pragma unroll
    for (int ii = 0; ii < 5; ii++) {
        int w = tye * 5 + ii;
        float M  = g_M[(b * NW + w) * NH + h];
        float Zi = 1.f / g_Z[(b * NW + w) * NH + h];
        #pragma unroll
        for (int pp = 0; pp < 5; pp++)
            *(float2*)&E[w * PADR + 2 * (txe * 5 + pp)] =
                make_float2(__expf(ef[ii][pp].x - M) * Zi,
                            __expf(ef[ii][pp].y - M) * Zi);
    }
    __syncthreads();

    int warp = t >> 5, lane = t & 31;
    float ow[4][5];
    attv16x40(E, vs, warp, lane, ow);
    float gm = gamma[0];
    __syncthreads();

    // load out_H slab (contiguous) into E region staged [w][c] pad 66
    {
        const float2* goh2 = (const float2*)(g_outH + ((size_t)b * NH + h) * NW * NC);
        for (int i2 = t; i2 < (NW * NC) / 2; i2 += 512) {
            int w2 = i2 >> 5, c2 = i2 & 31;
            *(float2*)&E[w2 * PADS + 2 * c2] = goh2[i2];
        }
    }
    __syncthreads();

    // combine into conv-input ob[c][w] (vs region, v fully consumed)
    {
        int cb = (warp & 3) * 16 + (lane & 3) * 4;
        int wb = (warp >> 2) * 40 + (lane >> 2) * 5;
        #pragma unroll
        for (int a = 0; a < 4; a++)
            #pragma unroll
            for (int r = 0; r < 5; r++) {
                int c = cb + a, w = wb + r;
                vs[c * PADR + w] = gm * (ow[a][r] + E[w * PADS + c]);
            }
    }
    __syncthreads();

    // grouped 1x1 conv + write o + BN partial sums (warp-uniform oc: 160 = 5*32)
    for (int i = t; i < NC * NW; i += 512) {
        int oc = i / NW, w = i - oc * NW;
        int g = oc >> 4;
        float a = 0.f;
        #pragma unroll
        for (int c = 0; c < 16; c++)
            a = fmaf(sw1[oc * 16 + c], vs[(16 * g + c) * PADR + w], a);
        g_o[((size_t)b * NC + oc) * NL + h * NW + w] = a;
        float s = a, q2 = a * a;
        #pragma unroll
        for (int off = 16; off > 0; off >>= 1) {
            s  += __shfl_xor_sync(0xffffffffu, s, off);
            q2 += __shfl_xor_sync(0xffffffffu, q2, off);
        }
        if ((t & 31) == 0) { atomicAdd(&csum[oc], s); atomicAdd(&csq[oc], q2); }
    }
    __syncthreads();
    if (t < NC) { atomicAdd(&g_sum[t], csum[t]); atomicAdd(&g_sumsq[t], csq[t]); }
}

// ---------------- K4: finalize BN scale/shift ------------------------------------
__global__ void k_bnfin(const float* __restrict__ bn_w, const float* __restrict__ bn_b)
{
    int c = threadIdx.x;
    const float invN = 1.f / (float)(NB * NL);
    float mean = g_sum[c] * invN;
    float var  = g_sumsq[c] * invN - mean * mean;
    float a    = bn_w[c] * rsqrtf(var + 1e-5f);
    g_bna[c] = a;
    g_bnb[c] = bn_b[c] - mean * a;
}

// ---------------- K5: BN apply + residual + ReLU (float4) ------------------------
__global__ __launch_bounds__(256) void k_final(const float* __restrict__ x, float* __restrict__ out)
{
    int i = blockIdx.x * 256 + threadIdx.x;          // float4 index
    int c = (i / 6400) & 63;
    float a = g_bna[c], bb = g_bnb[c];
    float4 o = ((const float4*)g_o)[i];
    float4 xv = ((const float4*)x)[i];
    float4 r;
    r.x = fmaf(o.x, a, bb) + xv.x; r.x = r.x > 0.f ? r.x : 0.f;
    r.y = fmaf(o.y, a, bb) + xv.y; r.y = r.y > 0.f ? r.y : 0.f;
    r.z = fmaf(o.z, a, bb) + xv.z; r.z = r.z > 0.f ? r.z : 0.f;
    r.w = fmaf(o.w, a, bb) + xv.w; r.w = r.w > 0.f ? r.w : 0.f;
    ((float4*)out)[i] = r;
}

// ---------------- host ------------------------------------------------------------
extern "C" void kernel_launch(void* const* d_in, const int* in_sizes, int n_in,
                              void* d_out, int out_size)
{
    (void)in_sizes; (void)n_in; (void)out_size;
    const float* x     = (const float*)d_in[0];
    const float* wq    = (const float*)d_in[1];
    const float* bq    = (const float*)d_in[2];
    const float* wk    = (const float*)d_in[3];
    const float* bk    = (const float*)d_in[4];
    const float* wv    = (const float*)d_in[5];
    const float* bv    = (const float*)d_in[6];
    const float* gamma = (const float*)d_in[7];
    const float* w1d   = (const float*)d_in[8];
    const float* bn_w  = (const float*)d_in[9];
    const float* bn_b  = (const float*)d_in[10];
    float* out = (float*)d_out;

    const int SMEM_BIG = (1296 * 2 + 160 * PADR + 64 * PADR) * 4;  // 155,520 B
    cudaFuncSetAttribute(k_colpass, cudaFuncAttributeMaxDynamicSharedMemorySize, SMEM_BIG);
    cudaFuncSetAttribute(k_rowpass, cudaFuncAttributeMaxDynamicSharedMemorySize, SMEM_BIG);

    k_zero<<<1, 64>>>();
    k_qkv<<<400, 128>>>(x, wq, bq, wk, bk, wv, bv);
    // z slices: 64 (q) + 64 (k) + 512 (v) = 640
    k_transpose_all<<<dim3(5, 5, 640), dim3(32, 8)>>>();
    k_ewstats<<<NB * NH, 512>>>();
    k_colpass<<<NB * NW, 512, SMEM_BIG>>>();
    k_rowpass<<<NB * NH, 512, SMEM_BIG>>>(gamma, w1d);
    k_bnfin<<<1, 64>>>(bn_w, bn_b);
    k_final<<<(NB * NC * NL) / 1024, 256>>>(x, out);
}